// round 13
// baseline (speedup 1.0000x reference)
#include <cuda_runtime.h>

#define BB 32
#define LL 64
#define NPAIRS 2016          // L*(L-1)/2
#define CHUNKS 32            // pair-chunks; 64 pairs per chunk
#define BPB 2                // batches per block

// Cross-block reduction scratch (zero at module load; kernel self-resets,
// so every call — correctness, capture, each graph replay — sees zeros).
__device__ float    g_acc[BB];
__device__ unsigned g_cnt[BB];

__global__ void __launch_bounds__(512) gp_kernel(
        const float* __restrict__ x,
        const float* __restrict__ th0,
        const float* __restrict__ th1,
        const float* __restrict__ th2,
        const float* __restrict__ th3,
        float* __restrict__ out) {
    const int chunk = blockIdx.x >> 4;       // [0,32) — pair-chunk
    const int bpair = blockIdx.x & 15;       // [0,16) — batch-pair
    const int tid   = threadIdx.x;
    const int j     = tid >> 8;              // which batch half [0,2)
    const int t     = tid & 255;             // thread within half
    const int b     = bpair * BPB + j;

    const int sub   = t & 3;                 // lane within 4-lane group
    const int grp   = t >> 2;                // group in half [0,64)
    const int w     = grp >> 3;              // warp-in-half [0,8)
    const int gi    = grp & 7;               // group-slot in warp [0,8)
    // balanced map: consecutive pairs within a warp (uniform trip count),
    // warps/chunks strided across the full l1 range
    const int p     = w * 256 + chunk * 8 + gi;   // [0,2048)

    __shared__ int   so_s[BPB][LL];   // flattened one-hot offsets o = l*4+c
    __shared__ float wsum[16];

    if (t < LL) {
        float4 v = ((const float4*)x)[b * LL + t];
        int c = v.y > 0.5f ? 1 : (v.z > 0.5f ? 2 : (v.w > 0.5f ? 3 : 0));
        so_s[j][t] = t * 4 + c;
    }
    __syncthreads();

    const int* __restrict__ so = so_s[j];

    float acc = 0.f;

    if (p < NPAIRS) {
        // branchless decode: p = l1*(l1-1)/2 + l0, l0 < l1
        int l1 = (int)((1.0f + sqrtf(8.0f * (float)p + 1.0f)) * 0.5f);
        if ((l1 * (l1 - 1)) >> 1 > p) l1--;
        if (((l1 + 1) * l1) >> 1 <= p) l1++;
        const int l0 = p - ((l1 * (l1 - 1)) >> 1);

        const int base2 = so[l0] * 256 + so[l1];
        float t2 = (sub == 0) ? th2[base2] : 0.f;     // order-2 term

        const float* __restrict__ row = th3 + (size_t)base2 * 256;
        const int l2b = l1 + 1 + sub;

        // one-hot dot == scalar selection: row[so[l2]].
        // Fully unrolled + predicated; 4 independent accumulator chains.
        float a0 = 0.f, a1 = 0.f, a2 = 0.f, a3 = 0.f;
        #pragma unroll
        for (int k = 0; k < 4; k++) {
            int i = l2b + 4 * k;
            if (i < LL) a0 += row[so[i]];
        }
        #pragma unroll
        for (int k = 4; k < 8; k++) {
            int i = l2b + 4 * k;
            if (i < LL) a1 += row[so[i]];
        }
        #pragma unroll
        for (int k = 8; k < 12; k++) {
            int i = l2b + 4 * k;
            if (i < LL) a2 += row[so[i]];
        }
        #pragma unroll
        for (int k = 12; k < 16; k++) {
            int i = l2b + 4 * k;
            if (i < LL) a3 += row[so[i]];
        }
        acc = (a0 + a1) + (a2 + a3) + t2;
    }

    // order 0 + 1, folded into chunk-0 blocks (first 64 threads of each half)
    if (chunk == 0 && t < LL) {
        acc += th1[so[t]];
        if (t == 0) acc += th0[0];
    }

    // intra-warp butterfly (each warp belongs to exactly one batch half)
    #pragma unroll
    for (int off = 16; off > 0; off >>= 1)
        acc += __shfl_xor_sync(0xffffffffu, acc, off);
    const int warp = tid >> 5;               // [0,16)
    if ((tid & 31) == 0) wsum[warp] = acc;
    __syncthreads();

    // one thread per half sums its 8 warps, atomicAdd, last-block finalize
    if (t == 0) {
        const int wb = j * 8;
        float s = 0.f;
        #pragma unroll
        for (int wi = 0; wi < 8; wi++) s += wsum[wb + wi];
        atomicAdd(&g_acc[b], s);
        __threadfence();
        unsigned done = atomicAdd(&g_cnt[b], 1u);
        if (done == CHUNKS - 1) {
            __threadfence();
            out[b] = g_acc[b];
            g_acc[b] = 0.f;      // reset for next replay
            g_cnt[b] = 0u;
        }
    }
}

extern "C" void kernel_launch(void* const* d_in, const int* in_sizes, int n_in,
                              void* d_out, int out_size) {
    const float* x   = (const float*)d_in[0];   // (B, L*C) one-hot
    const float* th0 = (const float*)d_in[1];   // (1,)
    const float* th1 = (const float*)d_in[2];   // (L, C)
    const float* th2 = (const float*)d_in[3];   // (L*C, L*C)
    const float* th3 = (const float*)d_in[4];   // (L*C, L*C, L*C)
    float* out = (float*)d_out;                 // (B, 1)

    gp_kernel<<<CHUNKS * (BB / BPB), 512>>>(x, th0, th1, th2, th3, out);
}